// round 14
// baseline (speedup 1.0000x reference)
#include <cuda_runtime.h>
#include <cuda_bf16.h>
#include <math.h>

#define THR 0.005f
#define EPSI 1e-5f
#define NBATCH 4
#define NNODE 4096
#define NCH 64
#define SP 136   // padded bf16 row stride (272B) -> conflict-free ldmatrix

typedef unsigned long long ull;
typedef unsigned int uint;

// ---------------- device scratch ----------------
__device__ __align__(16) float g_xt[NBATCH * NNODE * NCH];     // x transposed [b][n][c]
__device__ __align__(16) float g_snorm[NBATCH * NNODE];
__device__ __align__(16) float g_dinv[NBATCH * NNODE];
__device__ __align__(16) unsigned g_adjT[NBATCH * 128 * NNODE];       // bits [b][word_m][n]
__device__ __align__(16) unsigned short g_xs [NBATCH * NNODE * 128];  // bf16 split layer0 in [hi64|lo64]
__device__ __align__(16) unsigned short g_xs2[NBATCH * NNODE * 128];  // bf16 split layer1 in
// 3-way bf16 split planes, channel-major: [b][plane*64 + c][n], planes h,m,l
__device__ __align__(16) unsigned short g_xsp[NBATCH * 192 * NNODE];
// diffusion partials (2 m-halves), fp32 [half][b][n][c]
__device__ __align__(16) float g_lxp[2ULL * NBATCH * NNODE * NCH];

// ---------------- helpers ----------------
__device__ __forceinline__ void fma2(ull& d, ull a, ull b) {
    asm("fma.rn.f32x2 %0, %1, %2, %0;" : "+l"(d) : "l"(a), "l"(b));
}
__device__ __forceinline__ ull pack2(float x) {
    ull r; asm("mov.b64 %0, {%1, %1};" : "=l"(r) : "f"(x)); return r;
}
union F2U { ull u; float2 f; };

__device__ __forceinline__ uint bfpair(uint u) {
    return ((u & 1u) ? 0x3F80u : 0u) | ((u & 2u) ? 0x3F800000u : 0u);
}

#define MMA_BF16(c, a0_, a1_, a2_, a3_, b0_, b1_) \
    asm volatile("mma.sync.aligned.m16n8k16.row.col.f32.bf16.bf16.f32 " \
        "{%0,%1,%2,%3},{%4,%5,%6,%7},{%8,%9},{%0,%1,%2,%3};" \
        : "+f"((c)[0]), "+f"((c)[1]), "+f"((c)[2]), "+f"((c)[3]) \
        : "r"(a0_), "r"(a1_), "r"(a2_), "r"(a3_), "r"(b0_), "r"(b1_))

// ---------------- prep: transpose + node norms + 3-way bf16 split ----------------
__global__ void __launch_bounds__(256) k_prep(const float* __restrict__ x) {
    __shared__ float xs2[64][65];   // [node][channel]
    int b = blockIdx.y, n0 = blockIdx.x * 64;
    int t = threadIdx.x;
    int c = t >> 2, seg = t & 3;
    {
        const float* xp = x + (size_t)(b * 64 + c) * NNODE + n0 + seg * 16;
        #pragma unroll
        for (int j = 0; j < 16; j++) xs2[seg * 16 + j][c] = xp[j];
    }
    __syncthreads();

    if (t < 64) {
        float s = 0.f;
        #pragma unroll
        for (int cc = 0; cc < 64; cc++) { float v = xs2[t][cc]; s += v * v; }
        g_snorm[b * NNODE + n0 + t] = sqrtf(s);
    }

    {
        int node = t >> 2, q = t & 3;
        float* op = g_xt + (size_t)(b * NNODE + n0 + node) * 64 + q * 16;
        #pragma unroll
        for (int j4 = 0; j4 < 4; j4++) {
            float4 v;
            v.x = xs2[node][q * 16 + j4 * 4 + 0];
            v.y = xs2[node][q * 16 + j4 * 4 + 1];
            v.z = xs2[node][q * 16 + j4 * 4 + 2];
            v.w = xs2[node][q * 16 + j4 * 4 + 3];
            *(float4*)(op + j4 * 4) = v;
        }
    }

    {
        unsigned short hb[16], mb[16], lb[16];
        #pragma unroll
        for (int j = 0; j < 16; j++) {
            float v = xs2[seg * 16 + j][c];
            __nv_bfloat16 h = __float2bfloat16_rn(v);
            float r1 = v - __bfloat162float(h);
            __nv_bfloat16 m = __float2bfloat16_rn(r1);
            __nv_bfloat16 l = __float2bfloat16_rn(r1 - __bfloat162float(m));
            hb[j] = *(unsigned short*)&h;
            mb[j] = *(unsigned short*)&m;
            lb[j] = *(unsigned short*)&l;
        }
        unsigned short* op = g_xsp + ((size_t)b * 192 + c) * NNODE + n0 + seg * 16;
        const size_t PL = (size_t)64 * NNODE;
        #pragma unroll
        for (int j4 = 0; j4 < 4; j4++) {
            *(ushort4*)(op + j4 * 4)          = *(ushort4*)&hb[j4 * 4];
            *(ushort4*)(op + PL + j4 * 4)     = *(ushort4*)&mb[j4 * 4];
            *(ushort4*)(op + 2 * PL + j4 * 4) = *(ushort4*)&lb[j4 * 4];
        }
    }
}

// ---------------- Gram via bf16 mma, PAIR-stacked split (virtual K=256) -------
__global__ void __launch_bounds__(256) k_gram() {
    __shared__ __align__(16) unsigned short As[2][32][SP];
    __shared__ __align__(16) unsigned short Bs[2][32][SP];
    __shared__ float sns[128], sms[128];

    int b = blockIdx.y;
    int xid = blockIdx.x;
    int bj = (int)((sqrtf(8.f * xid + 1.f) - 1.f) * 0.5f);
    while ((bj + 1) * (bj + 2) / 2 <= xid) bj++;
    while (bj * (bj + 1) / 2 > xid) bj--;
    int bi = xid - bj * (bj + 1) / 2;
    int n0 = bi * 128, m0 = bj * 128;

    int t = threadIdx.x, warp = t >> 5, lane = t & 31;
    int wn = warp >> 1, wm = warp & 1;

    if (t < 128) sns[t] = g_snorm[b * NNODE + n0 + t];
    else         sms[t - 128] = g_snorm[b * NNODE + m0 + (t - 128)];

    const unsigned short* xp = g_xsp + (size_t)b * 192 * NNODE;
    int seg = t & 15, kr0 = t >> 4;

    uint sa = (uint)__cvta_generic_to_shared(&As[0][0][0]);
    uint sb = (uint)__cvta_generic_to_shared(&Bs[0][0][0]);
    const uint BUFB = 32 * SP * 2;

    #define STAGE(kc, buf) do { \
        int p_ = (kc) >> 1; \
        int ka_ = (p_ & 1) * 64 + ((kc) & 1) * 32; \
        int kb_ = ((p_ >> 1) & 1) * 64 + ((kc) & 1) * 32; \
        uint da = sa + (buf) * BUFB; uint db = sb + (buf) * BUFB; \
        const unsigned short* a0_ = xp + (size_t)(ka_ + kr0) * NNODE + n0; \
        const unsigned short* a1_ = xp + (size_t)(ka_ + kr0 + 16) * NNODE + n0; \
        const unsigned short* b0_ = xp + (size_t)(kb_ + kr0) * NNODE + m0; \
        const unsigned short* b1_ = xp + (size_t)(kb_ + kr0 + 16) * NNODE + m0; \
        asm volatile("cp.async.ca.shared.global [%0], [%1], 16;" \
            :: "r"(da + (uint)(kr0 * SP + seg * 8) * 2),        "l"(a0_ + seg * 8)); \
        asm volatile("cp.async.ca.shared.global [%0], [%1], 16;" \
            :: "r"(da + (uint)((kr0 + 16) * SP + seg * 8) * 2), "l"(a1_ + seg * 8)); \
        asm volatile("cp.async.ca.shared.global [%0], [%1], 16;" \
            :: "r"(db + (uint)(kr0 * SP + seg * 8) * 2),        "l"(b0_ + seg * 8)); \
        asm volatile("cp.async.ca.shared.global [%0], [%1], 16;" \
            :: "r"(db + (uint)((kr0 + 16) * SP + seg * 8) * 2), "l"(b1_ + seg * 8)); \
        asm volatile("cp.async.commit_group;"); \
    } while (0)

    float cc[2][8][4];
    #pragma unroll
    for (int t2 = 0; t2 < 2; t2++)
        #pragma unroll
        for (int j = 0; j < 8; j++)
            #pragma unroll
            for (int q = 0; q < 4; q++) cc[t2][j][q] = 0.f;

    STAGE(0, 0);
    STAGE(1, 1);

    int krl = (lane & 7) + ((lane >> 3) & 1) * 8;
    int chalf = (lane >> 4) * 8;

    for (int kc = 0; kc < 8; kc++) {
        if (kc < 7) asm volatile("cp.async.wait_group 1;" ::: "memory");
        else        asm volatile("cp.async.wait_group 0;" ::: "memory");
        __syncthreads();
        int buf = kc & 1;
        uint ab = sa + buf * BUFB;
        uint bb = sb + buf * BUFB;
        #pragma unroll
        for (int ks = 0; ks < 2; ks++) {
            int kr = ks * 16 + krl;
            uint a[2][4];
            #pragma unroll
            for (int t2 = 0; t2 < 2; t2++) {
                uint addr = ab + (uint)(kr * SP + wn * 32 + t2 * 16 + chalf) * 2;
                asm volatile(
                    "ldmatrix.sync.aligned.m8n8.x4.trans.shared.b16 {%0,%1,%2,%3}, [%4];"
                    : "=r"(a[t2][0]), "=r"(a[t2][1]), "=r"(a[t2][2]), "=r"(a[t2][3])
                    : "r"(addr));
            }
            #pragma unroll
            for (int mg = 0; mg < 4; mg++) {
                uint r0, r1, r2, r3;
                uint addr = bb + (uint)(kr * SP + wm * 64 + mg * 16 + chalf) * 2;
                asm volatile(
                    "ldmatrix.sync.aligned.m8n8.x4.trans.shared.b16 {%0,%1,%2,%3}, [%4];"
                    : "=r"(r0), "=r"(r1), "=r"(r2), "=r"(r3)
                    : "r"(addr));
                #pragma unroll
                for (int t2 = 0; t2 < 2; t2++) {
                    MMA_BF16(cc[t2][2 * mg],     a[t2][0], a[t2][2], a[t2][1], a[t2][3], r0, r1);
                    MMA_BF16(cc[t2][2 * mg + 1], a[t2][0], a[t2][2], a[t2][1], a[t2][3], r2, r3);
                }
            }
        }
        __syncthreads();
        if (kc + 2 < 8) STAGE(kc + 2, buf);
    }

    int q = lane & 3, gid = lane >> 2;
    uint cb[2][2];
    #pragma unroll
    for (int t2 = 0; t2 < 2; t2++) {
        #pragma unroll
        for (int rh = 0; rh < 2; rh++) {
            int rl = wn * 32 + t2 * 16 + rh * 8 + gid;
            float sn = sns[rl];
            uint c = 0;
            #pragma unroll
            for (int j = 0; j < 8; j++) {
                int ml = wm * 64 + j * 8 + 2 * q;
                uint c0 = (cc[t2][j][rh * 2]     > THR * (sn * sms[ml]))     ? 1u : 0u;
                uint c1 = (cc[t2][j][rh * 2 + 1] > THR * (sn * sms[ml + 1])) ? 1u : 0u;
                c |= (c0 << (2 * j)) | (c1 << (2 * j + 1));
            }
            cb[t2][rh] = c;
            uint w0 = 0, w1 = 0;
            #pragma unroll
            for (int j = 0; j < 4; j++) {
                w0 |= ((c >> (2 * j)) & 1u)     << (j * 8 + 2 * q);
                w0 |= ((c >> (2 * j + 1)) & 1u) << (j * 8 + 2 * q + 1);
                w1 |= ((c >> (2 * j + 8)) & 1u) << (j * 8 + 2 * q);
                w1 |= ((c >> (2 * j + 9)) & 1u) << (j * 8 + 2 * q + 1);
            }
            w0 |= __shfl_xor_sync(0xffffffffu, w0, 1);
            w0 |= __shfl_xor_sync(0xffffffffu, w0, 2);
            w1 |= __shfl_xor_sync(0xffffffffu, w1, 1);
            w1 |= __shfl_xor_sync(0xffffffffu, w1, 2);
            if (q == 0) {
                int gn = n0 + rl;
                g_adjT[((size_t)b * 128 + (m0 >> 5) + wm * 2)     * NNODE + gn] = w0;
                g_adjT[((size_t)b * 128 + (m0 >> 5) + wm * 2 + 1) * NNODE + gn] = w1;
            }
        }
    }
    if (bi != bj) {
        #pragma unroll
        for (int idx = 0; idx < 16; idx++) {
            uint v = ((cb[0][0] >> idx) & 1u) << gid
                   | ((cb[0][1] >> idx) & 1u) << (gid + 8)
                   | ((cb[1][0] >> idx) & 1u) << (gid + 16)
                   | ((cb[1][1] >> idx) & 1u) << (gid + 24);
            v |= __shfl_xor_sync(0xffffffffu, v, 4);
            v |= __shfl_xor_sync(0xffffffffu, v, 8);
            v |= __shfl_xor_sync(0xffffffffu, v, 16);
            if (gid == 0) {
                int mg = m0 + wm * 64 + (idx >> 1) * 8 + 2 * lane + (idx & 1);
                g_adjT[((size_t)b * 128 + (n0 >> 5) + wn) * NNODE + mg] = v;
            }
        }
    }
}

// ---------------- fused degree + dinv + layer0 split ----------------
__global__ void __launch_bounds__(128) k_degsplit() {
    __shared__ int sc[4][32];
    __shared__ float sdv[32];

    int i0 = blockIdx.x * 32;
    int t = threadIdx.x, q = t >> 5, lane = t & 31;
    int gi = i0 + lane;
    int b = gi >> 12, nl = gi & 4095;
    const unsigned* base = g_adjT + (size_t)b * 128 * NNODE + nl;
    int c = 0;
    #pragma unroll 8
    for (int j = 0; j < 32; j++)
        c += __popc(base[(size_t)(q * 32 + j) * NNODE]);
    sc[q][lane] = c;
    __syncthreads();
    if (t < 32) {
        int tot = sc[0][t] + sc[1][t] + sc[2][t] + sc[3][t];
        float d = 1.0f / sqrtf((float)tot);
        g_dinv[i0 + t] = d;
        sdv[t] = d;
    }
    __syncthreads();

    int node = i0 + (t >> 2);
    float d = sdv[t >> 2];
    const float4* src = (const float4*)(g_xt + (size_t)node * 64 + (t & 3) * 16);
    unsigned short* o = g_xs + (size_t)node * 128 + (t & 3) * 16;
    #pragma unroll
    for (int j = 0; j < 4; j++) {
        float4 v = src[j];
        v.x *= d; v.y *= d; v.z *= d; v.w *= d;
        __nv_bfloat16 h0 = __float2bfloat16_rn(v.x);
        __nv_bfloat16 h1 = __float2bfloat16_rn(v.y);
        __nv_bfloat16 h2 = __float2bfloat16_rn(v.z);
        __nv_bfloat16 h3 = __float2bfloat16_rn(v.w);
        __nv_bfloat16 l0 = __float2bfloat16_rn(v.x - __bfloat162float(h0));
        __nv_bfloat16 l1 = __float2bfloat16_rn(v.y - __bfloat162float(h1));
        __nv_bfloat16 l2 = __float2bfloat16_rn(v.z - __bfloat162float(h2));
        __nv_bfloat16 l3 = __float2bfloat16_rn(v.w - __bfloat162float(h3));
        ushort4 hh, ll;
        hh.x = *(unsigned short*)&h0; hh.y = *(unsigned short*)&h1;
        hh.z = *(unsigned short*)&h2; hh.w = *(unsigned short*)&h3;
        ll.x = *(unsigned short*)&l0; ll.y = *(unsigned short*)&l1;
        ll.z = *(unsigned short*)&l2; ll.w = *(unsigned short*)&l3;
        *(ushort4*)(o + j * 4)      = hh;
        *(ushort4*)(o + 64 + j * 4) = ll;
    }
}

// ---------------- diffusion mma partial over one m-half (R11 mainloop) -------
// Grid (64, 4, 2): 512 blocks. Block = 64 rows x 128 f, 32 chunks of this half.
// Writes raw fp32 partial (hi+lo combined, NO dinv) to g_lxp[half].
__global__ void __launch_bounds__(128) k_mm_part(int layer) {
    __shared__ __align__(16) unsigned short bs[2][64][SP];

    int b = blockIdx.y, n0 = blockIdx.x * 64, ms = blockIdx.z;
    int t = threadIdx.x, wr = t >> 5, lane = t & 31;
    int g = lane >> 2, tq = lane & 3;
    int rl8 = (lane & 7) + ((lane >> 3) & 1) * 8;
    int fg = (lane >> 4) * 8;

    const unsigned short* xsrc = (layer == 0) ? g_xs : g_xs2;
    const unsigned short* xsb = xsrc + (size_t)b * NNODE * 128 + (size_t)ms * 2048 * 128;
    const unsigned* pa = g_adjT + ((size_t)b * 128 + ms * 64) * NNODE + (n0 + wr * 16 + g);
    const unsigned* pa8 = pa + 8;

    float cc[16][4];
    #pragma unroll
    for (int j = 0; j < 16; j++)
        #pragma unroll
        for (int q = 0; q < 4; q++) cc[j][q] = 0.f;

    int srow = t >> 4, schk = t & 15;
    uint sb0 = (uint)__cvta_generic_to_shared(&bs[0][0][0]);
    uint sb1 = (uint)__cvta_generic_to_shared(&bs[1][0][0]);

    float4 pf[8];
    #pragma unroll
    for (int ps = 0; ps < 8; ps++)
        pf[ps] = *(const float4*)(xsb + (size_t)(srow + ps * 8) * 128 + schk * 8);
    #pragma unroll
    for (int ps = 0; ps < 8; ps++)
        *(float4*)&bs[0][srow + ps * 8][schk * 8] = pf[ps];
    #pragma unroll
    for (int ps = 0; ps < 8; ps++)
        pf[ps] = *(const float4*)(xsb + (size_t)(64 + srow + ps * 8) * 128 + schk * 8);
    unsigned w0a = pa[0], w1a = pa[(size_t)NNODE];
    unsigned w0b = pa8[0], w1b = pa8[(size_t)NNODE];

    for (int c = 0; c < 32; c++) {
        __syncthreads();
        if (c + 1 < 32) {
            #pragma unroll
            for (int ps = 0; ps < 8; ps++)
                *(float4*)&bs[(c + 1) & 1][srow + ps * 8][schk * 8] = pf[ps];
            if (c + 2 < 32) {
                #pragma unroll
                for (int ps = 0; ps < 8; ps++)
                    pf[ps] = *(const float4*)(xsb + (size_t)((c + 2) * 64 + srow + ps * 8) * 128 + schk * 8);
            }
        }
        unsigned nw0a = 0, nw1a = 0, nw0b = 0, nw1b = 0;
        if (c + 1 < 32) {
            nw0a = pa[(size_t)(2 * c + 2) * NNODE];
            nw1a = pa[(size_t)(2 * c + 3) * NNODE];
            nw0b = pa8[(size_t)(2 * c + 2) * NNODE];
            nw1b = pa8[(size_t)(2 * c + 3) * NNODE];
        }
        uint bb = (c & 1) ? sb1 : sb0;
        #pragma unroll
        for (int q = 0; q < 4; q++) {
            unsigned wA = (q < 2) ? w0a : w1a;
            unsigned wB = (q < 2) ? w0b : w1b;
            int s = ((q & 1) << 4) + 2 * tq;
            uint a0 = bfpair((wA >> s) & 3u);
            uint a2 = bfpair((wA >> (s + 8)) & 3u);
            uint a1 = bfpair((wB >> s) & 3u);
            uint a3 = bfpair((wB >> (s + 8)) & 3u);
            uint baddr = bb + (uint)(((q * 16 + rl8) * SP + fg) * 2);
            #pragma unroll
            for (int p = 0; p < 8; p++) {
                uint r0, r1, r2, r3;
                asm volatile(
                    "ldmatrix.sync.aligned.m8n8.x4.trans.shared.b16 {%0,%1,%2,%3}, [%4];"
                    : "=r"(r0), "=r"(r1), "=r"(r2), "=r"(r3)
                    : "r"(baddr + (uint)(p * 32)));
                MMA_BF16(cc[2 * p],     a0, a1, a2, a3, r0, r1);
                MMA_BF16(cc[2 * p + 1], a0, a1, a2, a3, r2, r3);
            }
        }
        w0a = nw0a; w1a = nw1a; w0b = nw0b; w1b = nw1b;
    }

    // write raw partial (hi+lo combine; dinv applied in k_fc)
    float* lp = g_lxp + (size_t)ms * (NBATCH * NNODE * NCH);
    int lr0 = wr * 16 + g;
    #pragma unroll
    for (int j = 0; j < 8; j++) {
        int col = j * 8 + 2 * tq;
        float2 u0 = make_float2(cc[j][0] + cc[j + 8][0], cc[j][1] + cc[j + 8][1]);
        float2 u1 = make_float2(cc[j][2] + cc[j + 8][2], cc[j][3] + cc[j + 8][3]);
        *(float2*)(lp + (size_t)(b * NNODE + n0 + lr0) * 64 + col)     = u0;
        *(float2*)(lp + (size_t)(b * NNODE + n0 + lr0 + 8) * 64 + col) = u1;
    }
}

// ---------------- FC + instance-norm + relu (combines 2 partials) ----------------
__global__ void __launch_bounds__(256) k_fc(int layer, const float* __restrict__ W,
                                            float* __restrict__ out_final) {
    __shared__ __align__(16) float lxs[64][68];
    __shared__ __align__(16) float ws[64][64];

    int b = blockIdx.y, n0 = blockIdx.x * 64;
    int t = threadIdx.x;
    int n = t >> 2, f0 = (t & 3) * 16;
    const size_t SL = (size_t)NBATCH * NNODE * NCH;

    {
        float dn = g_dinv[b * NNODE + n0 + n];
        size_t base = (size_t)(b * NNODE + n0 + n) * 64 + f0;
        #pragma unroll
        for (int j = 0; j < 4; j++) {
            float4 v0 = *(const float4*)(g_lxp + base + j * 4);
            float4 v1 = *(const float4*)(g_lxp + SL + base + j * 4);
            float4 v;
            v.x = (v0.x + v1.x) * dn; v.y = (v0.y + v1.y) * dn;
            v.z = (v0.z + v1.z) * dn; v.w = (v0.w + v1.w) * dn;
            *(float4*)&lxs[n][f0 + j * 4] = v;
        }
        const float4* gw = (const float4*)(W + n * 64 + (t & 3) * 16);
        float4* sw = (float4*)&ws[n][(t & 3) * 16];
        #pragma unroll
        for (int j = 0; j < 4; j++) sw[j] = gw[j];
    }
    __syncthreads();

    ull h[8];
    #pragma unroll
    for (int j = 0; j < 8; j++) h[j] = 0ULL;
    #pragma unroll 8
    for (int c = 0; c < 64; c++) {
        ull a2 = pack2(lxs[n][c]);
        ulonglong2 w0 = *(const ulonglong2*)&ws[c][f0];
        ulonglong2 w1 = *(const ulonglong2*)&ws[c][f0 + 4];
        ulonglong2 w2 = *(const ulonglong2*)&ws[c][f0 + 8];
        ulonglong2 w3 = *(const ulonglong2*)&ws[c][f0 + 12];
        fma2(h[0], a2, w0.x); fma2(h[1], a2, w0.y);
        fma2(h[2], a2, w1.x); fma2(h[3], a2, w1.y);
        fma2(h[4], a2, w2.x); fma2(h[5], a2, w2.y);
        fma2(h[6], a2, w3.x); fma2(h[7], a2, w3.y);
    }
    float hv[16];
    #pragma unroll
    for (int j = 0; j < 8; j++) { F2U u; u.u = h[j]; hv[2 * j] = u.f.x; hv[2 * j + 1] = u.f.y; }

    float s = 0.f;
    #pragma unroll
    for (int j = 0; j < 16; j++) s += hv[j];
    s += __shfl_xor_sync(0xffffffffu, s, 1);
    s += __shfl_xor_sync(0xffffffffu, s, 2);
    float mean = s * (1.f / 64.f);
    float vq = 0.f;
    #pragma unroll
    for (int j = 0; j < 16; j++) { float d = hv[j] - mean; vq += d * d; }
    vq += __shfl_xor_sync(0xffffffffu, vq, 1);
    vq += __shfl_xor_sync(0xffffffffu, vq, 2);
    float inv = 1.0f / sqrtf(vq * (1.f / 64.f) + EPSI);

    int gnode = b * NNODE + n0 + n;
    if (layer == 0) {
        float d = g_dinv[gnode];
        unsigned short* o = g_xs2 + (size_t)gnode * 128 + f0;
        #pragma unroll
        for (int f4 = 0; f4 < 4; f4++) {
            ushort4 hh, ll;
            unsigned short* hp = &hh.x;
            unsigned short* lp = &ll.x;
            #pragma unroll
            for (int q = 0; q < 4; q++) {
                float y = fmaxf((hv[f4 * 4 + q] - mean) * inv, 0.f) * d;
                __nv_bfloat16 hb = __float2bfloat16_rn(y);
                __nv_bfloat16 lb = __float2bfloat16_rn(y - __bfloat162float(hb));
                hp[q] = *(unsigned short*)&hb;
                lp[q] = *(unsigned short*)&lb;
            }
            *(ushort4*)(o + f4 * 4)      = hh;
            *(ushort4*)(o + 64 + f4 * 4) = ll;
        }
    } else {
        float* op = out_final + (size_t)gnode * 64 + f0;
        #pragma unroll
        for (int f4 = 0; f4 < 4; f4++) {
            float4 ov;
            ov.x = fmaxf((hv[f4 * 4 + 0] - mean) * inv, 0.f);
            ov.y = fmaxf((hv[f4 * 4 + 1] - mean) * inv, 0.f);
            ov.z = fmaxf((hv[f4 * 4 + 2] - mean) * inv, 0.f);
            ov.w = fmaxf((hv[f4 * 4 + 3] - mean) * inv, 0.f);
            *(float4*)(op + f4 * 4) = ov;
        }
    }
}

// ---------------- launch ----------------
extern "C" void kernel_launch(void* const* d_in, const int* in_sizes, int n_in,
                              void* d_out, int out_size) {
    const float* x  = (const float*)d_in[0];
    const float* W0 = (const float*)d_in[1];
    const float* W1 = (const float*)d_in[2];
    float* out = (float*)d_out;

    k_prep<<<dim3(64, 4), 256>>>(x);
    k_gram<<<dim3(528, 4), 256>>>();
    k_degsplit<<<512, 128>>>();
    k_mm_part<<<dim3(64, 4, 2), 128>>>(0);
    k_fc<<<dim3(64, 4), 256>>>(0, W0, nullptr);
    k_mm_part<<<dim3(64, 4, 2), 128>>>(1);
    k_fc<<<dim3(64, 4), 256>>>(1, W1, out);
}

// round 15
// speedup vs baseline: 1.3525x; 1.3525x over previous
#include <cuda_runtime.h>
#include <cuda_bf16.h>
#include <math.h>

#define THR 0.005f
#define EPSI 1e-5f
#define NBATCH 4
#define NNODE 4096
#define NCH 64
#define SP 136   // padded bf16 row stride (272B) -> conflict-free ldmatrix

typedef unsigned long long ull;
typedef unsigned int uint;

// ---------------- device scratch ----------------
__device__ __align__(16) float g_xt[NBATCH * NNODE * NCH];     // x transposed [b][n][c]
__device__ __align__(16) float g_snorm[NBATCH * NNODE];
__device__ __align__(16) float g_dinv[NBATCH * NNODE];
__device__ __align__(16) unsigned g_adjT[NBATCH * 128 * NNODE];       // bits [b][word_m][n]
__device__ __align__(16) unsigned short g_xs [NBATCH * NNODE * 128];  // bf16 split layer0 in [hi64|lo64]
__device__ __align__(16) unsigned short g_xs2[NBATCH * NNODE * 128];  // bf16 split layer1 in
// 3-way bf16 split planes, channel-major: [b][plane*64 + c][n], planes h,m,l
__device__ __align__(16) unsigned short g_xsp[NBATCH * 192 * NNODE];

// ---------------- helpers ----------------
__device__ __forceinline__ void fma2(ull& d, ull a, ull b) {
    asm("fma.rn.f32x2 %0, %1, %2, %0;" : "+l"(d) : "l"(a), "l"(b));
}
__device__ __forceinline__ ull pack2(float x) {
    ull r; asm("mov.b64 %0, {%1, %1};" : "=l"(r) : "f"(x)); return r;
}
union F2U { ull u; float2 f; };

__device__ __forceinline__ uint bfpair(uint u) {
    return ((u & 1u) ? 0x3F80u : 0u) | ((u & 2u) ? 0x3F800000u : 0u);
}

#define MMA_BF16(c, a0_, a1_, a2_, a3_, b0_, b1_) \
    asm volatile("mma.sync.aligned.m16n8k16.row.col.f32.bf16.bf16.f32 " \
        "{%0,%1,%2,%3},{%4,%5,%6,%7},{%8,%9},{%0,%1,%2,%3};" \
        : "+f"((c)[0]), "+f"((c)[1]), "+f"((c)[2]), "+f"((c)[3]) \
        : "r"(a0_), "r"(a1_), "r"(a2_), "r"(a3_), "r"(b0_), "r"(b1_))

// ---------------- prep: transpose + node norms + 3-way bf16 split ----------------
__global__ void __launch_bounds__(256) k_prep(const float* __restrict__ x) {
    __shared__ float xs2[64][65];   // [node][channel]
    int b = blockIdx.y, n0 = blockIdx.x * 64;
    int t = threadIdx.x;
    int c = t >> 2, seg = t & 3;
    {
        const float* xp = x + (size_t)(b * 64 + c) * NNODE + n0 + seg * 16;
        #pragma unroll
        for (int j = 0; j < 16; j++) xs2[seg * 16 + j][c] = xp[j];
    }
    __syncthreads();

    if (t < 64) {
        float s = 0.f;
        #pragma unroll
        for (int cc = 0; cc < 64; cc++) { float v = xs2[t][cc]; s += v * v; }
        g_snorm[b * NNODE + n0 + t] = sqrtf(s);
    }

    {
        int node = t >> 2, q = t & 3;
        float* op = g_xt + (size_t)(b * NNODE + n0 + node) * 64 + q * 16;
        #pragma unroll
        for (int j4 = 0; j4 < 4; j4++) {
            float4 v;
            v.x = xs2[node][q * 16 + j4 * 4 + 0];
            v.y = xs2[node][q * 16 + j4 * 4 + 1];
            v.z = xs2[node][q * 16 + j4 * 4 + 2];
            v.w = xs2[node][q * 16 + j4 * 4 + 3];
            *(float4*)(op + j4 * 4) = v;
        }
    }

    {
        unsigned short hb[16], mb[16], lb[16];
        #pragma unroll
        for (int j = 0; j < 16; j++) {
            float v = xs2[seg * 16 + j][c];
            __nv_bfloat16 h = __float2bfloat16_rn(v);
            float r1 = v - __bfloat162float(h);
            __nv_bfloat16 m = __float2bfloat16_rn(r1);
            __nv_bfloat16 l = __float2bfloat16_rn(r1 - __bfloat162float(m));
            hb[j] = *(unsigned short*)&h;
            mb[j] = *(unsigned short*)&m;
            lb[j] = *(unsigned short*)&l;
        }
        unsigned short* op = g_xsp + ((size_t)b * 192 + c) * NNODE + n0 + seg * 16;
        const size_t PL = (size_t)64 * NNODE;
        #pragma unroll
        for (int j4 = 0; j4 < 4; j4++) {
            *(ushort4*)(op + j4 * 4)          = *(ushort4*)&hb[j4 * 4];
            *(ushort4*)(op + PL + j4 * 4)     = *(ushort4*)&mb[j4 * 4];
            *(ushort4*)(op + 2 * PL + j4 * 4) = *(ushort4*)&lb[j4 * 4];
        }
    }
}

// ---------------- Gram via bf16 mma, PAIR-stacked split (virtual K=256) -------
__global__ void __launch_bounds__(256) k_gram() {
    __shared__ __align__(16) unsigned short As[2][32][SP];
    __shared__ __align__(16) unsigned short Bs[2][32][SP];
    __shared__ float sns[128], sms[128];

    int b = blockIdx.y;
    int xid = blockIdx.x;
    int bj = (int)((sqrtf(8.f * xid + 1.f) - 1.f) * 0.5f);
    while ((bj + 1) * (bj + 2) / 2 <= xid) bj++;
    while (bj * (bj + 1) / 2 > xid) bj--;
    int bi = xid - bj * (bj + 1) / 2;
    int n0 = bi * 128, m0 = bj * 128;

    int t = threadIdx.x, warp = t >> 5, lane = t & 31;
    int wn = warp >> 1, wm = warp & 1;

    if (t < 128) sns[t] = g_snorm[b * NNODE + n0 + t];
    else         sms[t - 128] = g_snorm[b * NNODE + m0 + (t - 128)];

    const unsigned short* xp = g_xsp + (size_t)b * 192 * NNODE;
    int seg = t & 15, kr0 = t >> 4;

    uint sa = (uint)__cvta_generic_to_shared(&As[0][0][0]);
    uint sb = (uint)__cvta_generic_to_shared(&Bs[0][0][0]);
    const uint BUFB = 32 * SP * 2;

    #define STAGE(kc, buf) do { \
        int p_ = (kc) >> 1; \
        int ka_ = (p_ & 1) * 64 + ((kc) & 1) * 32; \
        int kb_ = ((p_ >> 1) & 1) * 64 + ((kc) & 1) * 32; \
        uint da = sa + (buf) * BUFB; uint db = sb + (buf) * BUFB; \
        const unsigned short* a0_ = xp + (size_t)(ka_ + kr0) * NNODE + n0; \
        const unsigned short* a1_ = xp + (size_t)(ka_ + kr0 + 16) * NNODE + n0; \
        const unsigned short* b0_ = xp + (size_t)(kb_ + kr0) * NNODE + m0; \
        const unsigned short* b1_ = xp + (size_t)(kb_ + kr0 + 16) * NNODE + m0; \
        asm volatile("cp.async.ca.shared.global [%0], [%1], 16;" \
            :: "r"(da + (uint)(kr0 * SP + seg * 8) * 2),        "l"(a0_ + seg * 8)); \
        asm volatile("cp.async.ca.shared.global [%0], [%1], 16;" \
            :: "r"(da + (uint)((kr0 + 16) * SP + seg * 8) * 2), "l"(a1_ + seg * 8)); \
        asm volatile("cp.async.ca.shared.global [%0], [%1], 16;" \
            :: "r"(db + (uint)(kr0 * SP + seg * 8) * 2),        "l"(b0_ + seg * 8)); \
        asm volatile("cp.async.ca.shared.global [%0], [%1], 16;" \
            :: "r"(db + (uint)((kr0 + 16) * SP + seg * 8) * 2), "l"(b1_ + seg * 8)); \
        asm volatile("cp.async.commit_group;"); \
    } while (0)

    float cc[2][8][4];
    #pragma unroll
    for (int t2 = 0; t2 < 2; t2++)
        #pragma unroll
        for (int j = 0; j < 8; j++)
            #pragma unroll
            for (int q = 0; q < 4; q++) cc[t2][j][q] = 0.f;

    STAGE(0, 0);
    STAGE(1, 1);

    int krl = (lane & 7) + ((lane >> 3) & 1) * 8;
    int chalf = (lane >> 4) * 8;

    for (int kc = 0; kc < 8; kc++) {
        if (kc < 7) asm volatile("cp.async.wait_group 1;" ::: "memory");
        else        asm volatile("cp.async.wait_group 0;" ::: "memory");
        __syncthreads();
        int buf = kc & 1;
        uint ab = sa + buf * BUFB;
        uint bb = sb + buf * BUFB;
        #pragma unroll
        for (int ks = 0; ks < 2; ks++) {
            int kr = ks * 16 + krl;
            uint a[2][4];
            #pragma unroll
            for (int t2 = 0; t2 < 2; t2++) {
                uint addr = ab + (uint)(kr * SP + wn * 32 + t2 * 16 + chalf) * 2;
                asm volatile(
                    "ldmatrix.sync.aligned.m8n8.x4.trans.shared.b16 {%0,%1,%2,%3}, [%4];"
                    : "=r"(a[t2][0]), "=r"(a[t2][1]), "=r"(a[t2][2]), "=r"(a[t2][3])
                    : "r"(addr));
            }
            #pragma unroll
            for (int mg = 0; mg < 4; mg++) {
                uint r0, r1, r2, r3;
                uint addr = bb + (uint)(kr * SP + wm * 64 + mg * 16 + chalf) * 2;
                asm volatile(
                    "ldmatrix.sync.aligned.m8n8.x4.trans.shared.b16 {%0,%1,%2,%3}, [%4];"
                    : "=r"(r0), "=r"(r1), "=r"(r2), "=r"(r3)
                    : "r"(addr));
                #pragma unroll
                for (int t2 = 0; t2 < 2; t2++) {
                    MMA_BF16(cc[t2][2 * mg],     a[t2][0], a[t2][2], a[t2][1], a[t2][3], r0, r1);
                    MMA_BF16(cc[t2][2 * mg + 1], a[t2][0], a[t2][2], a[t2][1], a[t2][3], r2, r3);
                }
            }
        }
        __syncthreads();
        if (kc + 2 < 8) STAGE(kc + 2, buf);
    }

    int q = lane & 3, gid = lane >> 2;
    uint cb[2][2];
    #pragma unroll
    for (int t2 = 0; t2 < 2; t2++) {
        #pragma unroll
        for (int rh = 0; rh < 2; rh++) {
            int rl = wn * 32 + t2 * 16 + rh * 8 + gid;
            float sn = sns[rl];
            uint c = 0;
            #pragma unroll
            for (int j = 0; j < 8; j++) {
                int ml = wm * 64 + j * 8 + 2 * q;
                uint c0 = (cc[t2][j][rh * 2]     > THR * (sn * sms[ml]))     ? 1u : 0u;
                uint c1 = (cc[t2][j][rh * 2 + 1] > THR * (sn * sms[ml + 1])) ? 1u : 0u;
                c |= (c0 << (2 * j)) | (c1 << (2 * j + 1));
            }
            cb[t2][rh] = c;
            uint w0 = 0, w1 = 0;
            #pragma unroll
            for (int j = 0; j < 4; j++) {
                w0 |= ((c >> (2 * j)) & 1u)     << (j * 8 + 2 * q);
                w0 |= ((c >> (2 * j + 1)) & 1u) << (j * 8 + 2 * q + 1);
                w1 |= ((c >> (2 * j + 8)) & 1u) << (j * 8 + 2 * q);
                w1 |= ((c >> (2 * j + 9)) & 1u) << (j * 8 + 2 * q + 1);
            }
            w0 |= __shfl_xor_sync(0xffffffffu, w0, 1);
            w0 |= __shfl_xor_sync(0xffffffffu, w0, 2);
            w1 |= __shfl_xor_sync(0xffffffffu, w1, 1);
            w1 |= __shfl_xor_sync(0xffffffffu, w1, 2);
            if (q == 0) {
                int gn = n0 + rl;
                g_adjT[((size_t)b * 128 + (m0 >> 5) + wm * 2)     * NNODE + gn] = w0;
                g_adjT[((size_t)b * 128 + (m0 >> 5) + wm * 2 + 1) * NNODE + gn] = w1;
            }
        }
    }
    if (bi != bj) {
        #pragma unroll
        for (int idx = 0; idx < 16; idx++) {
            uint v = ((cb[0][0] >> idx) & 1u) << gid
                   | ((cb[0][1] >> idx) & 1u) << (gid + 8)
                   | ((cb[1][0] >> idx) & 1u) << (gid + 16)
                   | ((cb[1][1] >> idx) & 1u) << (gid + 24);
            v |= __shfl_xor_sync(0xffffffffu, v, 4);
            v |= __shfl_xor_sync(0xffffffffu, v, 8);
            v |= __shfl_xor_sync(0xffffffffu, v, 16);
            if (gid == 0) {
                int mg = m0 + wm * 64 + (idx >> 1) * 8 + 2 * lane + (idx & 1);
                g_adjT[((size_t)b * 128 + (n0 >> 5) + wn) * NNODE + mg] = v;
            }
        }
    }
}

// ---------------- fused degree + dinv + layer0 split ----------------
__global__ void __launch_bounds__(128) k_degsplit() {
    __shared__ int sc[4][32];
    __shared__ float sdv[32];

    int i0 = blockIdx.x * 32;
    int t = threadIdx.x, q = t >> 5, lane = t & 31;
    int gi = i0 + lane;
    int b = gi >> 12, nl = gi & 4095;
    const unsigned* base = g_adjT + (size_t)b * 128 * NNODE + nl;
    int c = 0;
    #pragma unroll 8
    for (int j = 0; j < 32; j++)
        c += __popc(base[(size_t)(q * 32 + j) * NNODE]);
    sc[q][lane] = c;
    __syncthreads();
    if (t < 32) {
        int tot = sc[0][t] + sc[1][t] + sc[2][t] + sc[3][t];
        float d = 1.0f / sqrtf((float)tot);
        g_dinv[i0 + t] = d;
        sdv[t] = d;
    }
    __syncthreads();

    int node = i0 + (t >> 2);
    float d = sdv[t >> 2];
    const float4* src = (const float4*)(g_xt + (size_t)node * 64 + (t & 3) * 16);
    unsigned short* o = g_xs + (size_t)node * 128 + (t & 3) * 16;
    #pragma unroll
    for (int j = 0; j < 4; j++) {
        float4 v = src[j];
        v.x *= d; v.y *= d; v.z *= d; v.w *= d;
        __nv_bfloat16 h0 = __float2bfloat16_rn(v.x);
        __nv_bfloat16 h1 = __float2bfloat16_rn(v.y);
        __nv_bfloat16 h2 = __float2bfloat16_rn(v.z);
        __nv_bfloat16 h3 = __float2bfloat16_rn(v.w);
        __nv_bfloat16 l0 = __float2bfloat16_rn(v.x - __bfloat162float(h0));
        __nv_bfloat16 l1 = __float2bfloat16_rn(v.y - __bfloat162float(h1));
        __nv_bfloat16 l2 = __float2bfloat16_rn(v.z - __bfloat162float(h2));
        __nv_bfloat16 l3 = __float2bfloat16_rn(v.w - __bfloat162float(h3));
        ushort4 hh, ll;
        hh.x = *(unsigned short*)&h0; hh.y = *(unsigned short*)&h1;
        hh.z = *(unsigned short*)&h2; hh.w = *(unsigned short*)&h3;
        ll.x = *(unsigned short*)&l0; ll.y = *(unsigned short*)&l1;
        ll.z = *(unsigned short*)&l2; ll.w = *(unsigned short*)&l3;
        *(ushort4*)(o + j * 4)      = hh;
        *(ushort4*)(o + 64 + j * 4) = ll;
    }
}

// ---------------- fused diffusion mma + FC + instance-norm + relu ----------------
// R11 structure; B-tile staging converted to cp.async double-buffer.
__global__ void __launch_bounds__(128) k_mm(int layer, float* __restrict__ out_final,
                                            const float* __restrict__ W) {
    __shared__ union {
        unsigned short bs[2][64][SP];
        struct { float lxs[64][68]; float ws[64][64]; } e;
    } SM;

    int b = blockIdx.y, n0 = blockIdx.x * 64;
    int t = threadIdx.x, wr = t >> 5, lane = t & 31;
    int g = lane >> 2, tq = lane & 3;
    int rl8 = (lane & 7) + ((lane >> 3) & 1) * 8;
    int fg = (lane >> 4) * 8;

    const unsigned short* xsrc = (layer == 0) ? g_xs : g_xs2;
    const unsigned short* xsb = xsrc + (size_t)b * NNODE * 128;
    const unsigned* pa = g_adjT + (size_t)b * 128 * NNODE + (n0 + wr * 16 + g);
    const unsigned* pa8 = pa + 8;

    float cc[16][4];
    #pragma unroll
    for (int j = 0; j < 16; j++)
        #pragma unroll
        for (int q = 0; q < 4; q++) cc[j][q] = 0.f;

    int srow = t >> 4, schk = t & 15;
    uint sb0 = (uint)__cvta_generic_to_shared(&SM.bs[0][0][0]);
    uint sb1 = (uint)__cvta_generic_to_shared(&SM.bs[1][0][0]);

    // cp.async staging: thread t stages rows srow+ps*8, 16B segment schk
    #define MM_STAGE(cc_, bufaddr) do { \
        const unsigned short* src_ = xsb + (size_t)(cc_) * 64 * 128; \
        _Pragma("unroll") \
        for (int ps = 0; ps < 8; ps++) { \
            asm volatile("cp.async.ca.shared.global [%0], [%1], 16;" \
                :: "r"((bufaddr) + (uint)((srow + ps * 8) * SP + schk * 8) * 2), \
                   "l"(src_ + (size_t)(srow + ps * 8) * 128 + schk * 8)); \
        } \
        asm volatile("cp.async.commit_group;"); \
    } while (0)

    MM_STAGE(0, sb0);
    unsigned w0a = pa[0], w1a = pa[(size_t)4096];
    unsigned w0b = pa8[0], w1b = pa8[(size_t)4096];

    for (int c = 0; c < 64; c++) {
        asm volatile("cp.async.wait_group 0;" ::: "memory");
        __syncthreads();
        if (c + 1 < 64) MM_STAGE(c + 1, (c & 1) ? sb0 : sb1);
        unsigned nw0a = 0, nw1a = 0, nw0b = 0, nw1b = 0;
        if (c + 1 < 64) {
            nw0a = pa[(size_t)(2 * c + 2) * 4096];
            nw1a = pa[(size_t)(2 * c + 3) * 4096];
            nw0b = pa8[(size_t)(2 * c + 2) * 4096];
            nw1b = pa8[(size_t)(2 * c + 3) * 4096];
        }
        uint bb = (c & 1) ? sb1 : sb0;
        #pragma unroll
        for (int q = 0; q < 4; q++) {
            unsigned wA = (q < 2) ? w0a : w1a;
            unsigned wB = (q < 2) ? w0b : w1b;
            int s = ((q & 1) << 4) + 2 * tq;
            uint a0 = bfpair((wA >> s) & 3u);
            uint a2 = bfpair((wA >> (s + 8)) & 3u);
            uint a1 = bfpair((wB >> s) & 3u);
            uint a3 = bfpair((wB >> (s + 8)) & 3u);
            uint baddr = bb + (uint)(((q * 16 + rl8) * SP + fg) * 2);
            #pragma unroll
            for (int p = 0; p < 8; p++) {
                uint r0, r1, r2, r3;
                asm volatile(
                    "ldmatrix.sync.aligned.m8n8.x4.trans.shared.b16 {%0,%1,%2,%3}, [%4];"
                    : "=r"(r0), "=r"(r1), "=r"(r2), "=r"(r3)
                    : "r"(baddr + (uint)(p * 32)));
                MMA_BF16(cc[2 * p],     a0, a1, a2, a3, r0, r1);
                MMA_BF16(cc[2 * p + 1], a0, a1, a2, a3, r2, r3);
            }
        }
        w0a = nw0a; w1a = nw1a; w0b = nw0b; w1b = nw1b;
        __syncthreads();   // compute done before next chunk's cp.async lands in this buffer's sibling
    }
    __syncthreads();

    {
        int lr0 = wr * 16 + g;
        float dn0 = g_dinv[b * NNODE + n0 + lr0];
        float dn1 = g_dinv[b * NNODE + n0 + lr0 + 8];
        #pragma unroll
        for (int j = 0; j < 8; j++) {
            int col = j * 8 + 2 * tq;
            float2 u0 = make_float2((cc[j][0] + cc[j + 8][0]) * dn0,
                                    (cc[j][1] + cc[j + 8][1]) * dn0);
            float2 u1 = make_float2((cc[j][2] + cc[j + 8][2]) * dn1,
                                    (cc[j][3] + cc[j + 8][3]) * dn1);
            *(float2*)&SM.e.lxs[lr0][col]     = u0;
            *(float2*)&SM.e.lxs[lr0 + 8][col] = u1;
        }
    }
    {
        int c2 = t >> 1, fh = (t & 1) * 32;
        #pragma unroll
        for (int j = 0; j < 8; j++)
            *(float4*)&SM.e.ws[c2][fh + j * 4] = *(const float4*)(W + c2 * 64 + fh + j * 4);
    }
    __syncthreads();

    int row = t >> 1, fh = (t & 1) * 32;
    ull h[16];
    #pragma unroll
    for (int j = 0; j < 16; j++) h[j] = 0ULL;
    #pragma unroll 8
    for (int c = 0; c < 64; c++) {
        ull a2 = pack2(SM.e.lxs[row][c]);
        const ulonglong2* w2 = (const ulonglong2*)&SM.e.ws[c][fh];
        #pragma unroll
        for (int j = 0; j < 4; j++) {
            ulonglong2 u0 = w2[2 * j];
            ulonglong2 u1 = w2[2 * j + 1];
            fma2(h[4 * j],     a2, u0.x);
            fma2(h[4 * j + 1], a2, u0.y);
            fma2(h[4 * j + 2], a2, u1.x);
            fma2(h[4 * j + 3], a2, u1.y);
        }
    }
    float hv[32];
    #pragma unroll
    for (int j = 0; j < 16; j++) { F2U u; u.u = h[j]; hv[2 * j] = u.f.x; hv[2 * j + 1] = u.f.y; }

    float sum = 0.f;
    #pragma unroll
    for (int j = 0; j < 32; j++) sum += hv[j];
    sum += __shfl_xor_sync(0xffffffffu, sum, 1);
    float mean = sum * (1.f / 64.f);
    float vq = 0.f;
    #pragma unroll
    for (int j = 0; j < 32; j++) { float d = hv[j] - mean; vq += d * d; }
    vq += __shfl_xor_sync(0xffffffffu, vq, 1);
    float inv = 1.0f / sqrtf(vq * (1.f / 64.f) + EPSI);

    int gnode = b * NNODE + n0 + row;
    if (layer == 0) {
        float d = g_dinv[gnode];
        unsigned short* o = g_xs2 + (size_t)gnode * 128 + fh;
        #pragma unroll
        for (int f4 = 0; f4 < 8; f4++) {
            ushort4 hh, ll;
            unsigned short* hp = &hh.x;
            unsigned short* lp = &ll.x;
            #pragma unroll
            for (int q = 0; q < 4; q++) {
                float y = fmaxf((hv[f4 * 4 + q] - mean) * inv, 0.f) * d;
                __nv_bfloat16 hb = __float2bfloat16_rn(y);
                __nv_bfloat16 lb = __float2bfloat16_rn(y - __bfloat162float(hb));
                hp[q] = *(unsigned short*)&hb;
                lp[q] = *(unsigned short*)&lb;
            }
            *(ushort4*)(o + f4 * 4)      = hh;
            *(ushort4*)(o + 64 + f4 * 4) = ll;
        }
    } else {
        float* op = out_final + (size_t)gnode * 64 + fh;
        #pragma unroll
        for (int f4 = 0; f4 < 8; f4++) {
            float4 ov;
            ov.x = fmaxf((hv[f4 * 4 + 0] - mean) * inv, 0.f);
            ov.y = fmaxf((hv[f4 * 4 + 1] - mean) * inv, 0.f);
            ov.z = fmaxf((hv[f4 * 4 + 2] - mean) * inv, 0.f);
            ov.w = fmaxf((hv[f4 * 4 + 3] - mean) * inv, 0.f);
            *(float4*)(op + f4 * 4) = ov;
        }
    }
}

// ---------------- launch ----------------
extern "C" void kernel_launch(void* const* d_in, const int* in_sizes, int n_in,
                              void* d_out, int out_size) {
    const float* x  = (const float*)d_in[0];
    const float* W0 = (const float*)d_in[1];
    const float* W1 = (const float*)d_in[2];
    float* out = (float*)d_out;

    k_prep<<<dim3(64, 4), 256>>>(x);
    k_gram<<<dim3(528, 4), 256>>>();
    k_degsplit<<<512, 128>>>();
    k_mm<<<dim3(64, 4), 128>>>(0, nullptr, W0);
    k_mm<<<dim3(64, 4), 128>>>(1, out, W1);
}

// round 16
// speedup vs baseline: 1.4293x; 1.0568x over previous
#include <cuda_runtime.h>
#include <cuda_bf16.h>
#include <math.h>

#define THR 0.005f
#define EPSI 1e-5f
#define NBATCH 4
#define NNODE 4096
#define NCH 64
#define SP 136   // padded bf16 row stride (272B) -> conflict-free ldmatrix

typedef unsigned long long ull;
typedef unsigned int uint;

// ---------------- device scratch ----------------
__device__ __align__(16) float g_xt[NBATCH * NNODE * NCH];     // x transposed [b][n][c]
__device__ __align__(16) float g_snorm[NBATCH * NNODE];
__device__ __align__(16) float g_dinv[NBATCH * NNODE];
__device__ __align__(16) unsigned g_adjT[NBATCH * 128 * NNODE];       // bits [b][word_m][n]
__device__ __align__(16) unsigned short g_xs [NBATCH * NNODE * 128];  // bf16 split layer0 in [hi64|lo64]
__device__ __align__(16) unsigned short g_xs2[NBATCH * NNODE * 128];  // bf16 split layer1 in
// 3-way bf16 split planes, channel-major: [b][plane*64 + c][n], planes h,m,l
__device__ __align__(16) unsigned short g_xsp[NBATCH * 192 * NNODE];

// ---------------- helpers ----------------
__device__ __forceinline__ void fma2(ull& d, ull a, ull b) {
    asm("fma.rn.f32x2 %0, %1, %2, %0;" : "+l"(d) : "l"(a), "l"(b));
}
__device__ __forceinline__ ull pack2(float x) {
    ull r; asm("mov.b64 %0, {%1, %1};" : "=l"(r) : "f"(x)); return r;
}
union F2U { ull u; float2 f; };

__device__ __forceinline__ uint bfpair(uint u) {
    return ((u & 1u) ? 0x3F80u : 0u) | ((u & 2u) ? 0x3F800000u : 0u);
}

#define MMA_BF16(c, a0_, a1_, a2_, a3_, b0_, b1_) \
    asm volatile("mma.sync.aligned.m16n8k16.row.col.f32.bf16.bf16.f32 " \
        "{%0,%1,%2,%3},{%4,%5,%6,%7},{%8,%9},{%0,%1,%2,%3};" \
        : "+f"((c)[0]), "+f"((c)[1]), "+f"((c)[2]), "+f"((c)[3]) \
        : "r"(a0_), "r"(a1_), "r"(a2_), "r"(a3_), "r"(b0_), "r"(b1_))

// ---------------- prep: transpose + node norms + 3-way bf16 split ----------------
__global__ void __launch_bounds__(256) k_prep(const float* __restrict__ x) {
    __shared__ float xs2[64][65];   // [node][channel]
    int b = blockIdx.y, n0 = blockIdx.x * 64;
    int t = threadIdx.x;
    int c = t >> 2, seg = t & 3;
    {
        const float* xp = x + (size_t)(b * 64 + c) * NNODE + n0 + seg * 16;
        #pragma unroll
        for (int j = 0; j < 16; j++) xs2[seg * 16 + j][c] = xp[j];
    }
    __syncthreads();

    if (t < 64) {
        float s = 0.f;
        #pragma unroll
        for (int cc = 0; cc < 64; cc++) { float v = xs2[t][cc]; s += v * v; }
        g_snorm[b * NNODE + n0 + t] = sqrtf(s);
    }

    {
        int node = t >> 2, q = t & 3;
        float* op = g_xt + (size_t)(b * NNODE + n0 + node) * 64 + q * 16;
        #pragma unroll
        for (int j4 = 0; j4 < 4; j4++) {
            float4 v;
            v.x = xs2[node][q * 16 + j4 * 4 + 0];
            v.y = xs2[node][q * 16 + j4 * 4 + 1];
            v.z = xs2[node][q * 16 + j4 * 4 + 2];
            v.w = xs2[node][q * 16 + j4 * 4 + 3];
            *(float4*)(op + j4 * 4) = v;
        }
    }

    {
        unsigned short hb[16], mb[16], lb[16];
        #pragma unroll
        for (int j = 0; j < 16; j++) {
            float v = xs2[seg * 16 + j][c];
            __nv_bfloat16 h = __float2bfloat16_rn(v);
            float r1 = v - __bfloat162float(h);
            __nv_bfloat16 m = __float2bfloat16_rn(r1);
            __nv_bfloat16 l = __float2bfloat16_rn(r1 - __bfloat162float(m));
            hb[j] = *(unsigned short*)&h;
            mb[j] = *(unsigned short*)&m;
            lb[j] = *(unsigned short*)&l;
        }
        unsigned short* op = g_xsp + ((size_t)b * 192 + c) * NNODE + n0 + seg * 16;
        const size_t PL = (size_t)64 * NNODE;
        #pragma unroll
        for (int j4 = 0; j4 < 4; j4++) {
            *(ushort4*)(op + j4 * 4)          = *(ushort4*)&hb[j4 * 4];
            *(ushort4*)(op + PL + j4 * 4)     = *(ushort4*)&mb[j4 * 4];
            *(ushort4*)(op + 2 * PL + j4 * 4) = *(ushort4*)&lb[j4 * 4];
        }
    }
}

// ---------------- Gram via bf16 mma, PAIR-stacked split (virtual K=192) -------
// Pairs (A,B): (h,h),(m,h),(h,m) = (h+m)(h'+m')^T - mm'^T. Missing terms
// ~2^-15 of x.x' -> rel_err ~1e-4. 6 chunks of 32 k-rows, double-buffered.
__global__ void __launch_bounds__(256) k_gram() {
    __shared__ __align__(16) unsigned short As[2][32][SP];
    __shared__ __align__(16) unsigned short Bs[2][32][SP];
    __shared__ float sns[128], sms[128];

    int b = blockIdx.y;
    int xid = blockIdx.x;
    int bj = (int)((sqrtf(8.f * xid + 1.f) - 1.f) * 0.5f);
    while ((bj + 1) * (bj + 2) / 2 <= xid) bj++;
    while (bj * (bj + 1) / 2 > xid) bj--;
    int bi = xid - bj * (bj + 1) / 2;
    int n0 = bi * 128, m0 = bj * 128;

    int t = threadIdx.x, warp = t >> 5, lane = t & 31;
    int wn = warp >> 1, wm = warp & 1;

    if (t < 128) sns[t] = g_snorm[b * NNODE + n0 + t];
    else         sms[t - 128] = g_snorm[b * NNODE + m0 + (t - 128)];

    const unsigned short* xp = g_xsp + (size_t)b * 192 * NNODE;
    int seg = t & 15, kr0 = t >> 4;

    uint sa = (uint)__cvta_generic_to_shared(&As[0][0][0]);
    uint sb = (uint)__cvta_generic_to_shared(&Bs[0][0][0]);
    const uint BUFB = 32 * SP * 2;

    // pair p = kc>>1 in {0,1,2}: A plane = p&1 (h,m,h); B plane = p>>1 (h,h,m)
    #define STAGE(kc, buf) do { \
        int p_ = (kc) >> 1; \
        int ka_ = (p_ & 1) * 64 + ((kc) & 1) * 32; \
        int kb_ = ((p_ >> 1) & 1) * 64 + ((kc) & 1) * 32; \
        uint da = sa + (buf) * BUFB; uint db = sb + (buf) * BUFB; \
        const unsigned short* a0_ = xp + (size_t)(ka_ + kr0) * NNODE + n0; \
        const unsigned short* a1_ = xp + (size_t)(ka_ + kr0 + 16) * NNODE + n0; \
        const unsigned short* b0_ = xp + (size_t)(kb_ + kr0) * NNODE + m0; \
        const unsigned short* b1_ = xp + (size_t)(kb_ + kr0 + 16) * NNODE + m0; \
        asm volatile("cp.async.ca.shared.global [%0], [%1], 16;" \
            :: "r"(da + (uint)(kr0 * SP + seg * 8) * 2),        "l"(a0_ + seg * 8)); \
        asm volatile("cp.async.ca.shared.global [%0], [%1], 16;" \
            :: "r"(da + (uint)((kr0 + 16) * SP + seg * 8) * 2), "l"(a1_ + seg * 8)); \
        asm volatile("cp.async.ca.shared.global [%0], [%1], 16;" \
            :: "r"(db + (uint)(kr0 * SP + seg * 8) * 2),        "l"(b0_ + seg * 8)); \
        asm volatile("cp.async.ca.shared.global [%0], [%1], 16;" \
            :: "r"(db + (uint)((kr0 + 16) * SP + seg * 8) * 2), "l"(b1_ + seg * 8)); \
        asm volatile("cp.async.commit_group;"); \
    } while (0)

    float cc[2][8][4];
    #pragma unroll
    for (int t2 = 0; t2 < 2; t2++)
        #pragma unroll
        for (int j = 0; j < 8; j++)
            #pragma unroll
            for (int q = 0; q < 4; q++) cc[t2][j][q] = 0.f;

    STAGE(0, 0);
    STAGE(1, 1);

    int krl = (lane & 7) + ((lane >> 3) & 1) * 8;
    int chalf = (lane >> 4) * 8;

    for (int kc = 0; kc < 6; kc++) {
        if (kc < 5) asm volatile("cp.async.wait_group 1;" ::: "memory");
        else        asm volatile("cp.async.wait_group 0;" ::: "memory");
        __syncthreads();
        int buf = kc & 1;
        uint ab = sa + buf * BUFB;
        uint bb = sb + buf * BUFB;
        #pragma unroll
        for (int ks = 0; ks < 2; ks++) {
            int kr = ks * 16 + krl;
            uint a[2][4];
            #pragma unroll
            for (int t2 = 0; t2 < 2; t2++) {
                uint addr = ab + (uint)(kr * SP + wn * 32 + t2 * 16 + chalf) * 2;
                asm volatile(
                    "ldmatrix.sync.aligned.m8n8.x4.trans.shared.b16 {%0,%1,%2,%3}, [%4];"
                    : "=r"(a[t2][0]), "=r"(a[t2][1]), "=r"(a[t2][2]), "=r"(a[t2][3])
                    : "r"(addr));
            }
            #pragma unroll
            for (int mg = 0; mg < 4; mg++) {
                uint r0, r1, r2, r3;
                uint addr = bb + (uint)(kr * SP + wm * 64 + mg * 16 + chalf) * 2;
                asm volatile(
                    "ldmatrix.sync.aligned.m8n8.x4.trans.shared.b16 {%0,%1,%2,%3}, [%4];"
                    : "=r"(r0), "=r"(r1), "=r"(r2), "=r"(r3)
                    : "r"(addr));
                #pragma unroll
                for (int t2 = 0; t2 < 2; t2++) {
                    MMA_BF16(cc[t2][2 * mg],     a[t2][0], a[t2][2], a[t2][1], a[t2][3], r0, r1);
                    MMA_BF16(cc[t2][2 * mg + 1], a[t2][0], a[t2][2], a[t2][1], a[t2][3], r2, r3);
                }
            }
        }
        __syncthreads();
        if (kc + 2 < 6) STAGE(kc + 2, buf);
    }

    int q = lane & 3, gid = lane >> 2;
    uint cb[2][2];
    #pragma unroll
    for (int t2 = 0; t2 < 2; t2++) {
        #pragma unroll
        for (int rh = 0; rh < 2; rh++) {
            int rl = wn * 32 + t2 * 16 + rh * 8 + gid;
            float sn = sns[rl];
            uint c = 0;
            #pragma unroll
            for (int j = 0; j < 8; j++) {
                int ml = wm * 64 + j * 8 + 2 * q;
                uint c0 = (cc[t2][j][rh * 2]     > THR * (sn * sms[ml]))     ? 1u : 0u;
                uint c1 = (cc[t2][j][rh * 2 + 1] > THR * (sn * sms[ml + 1])) ? 1u : 0u;
                c |= (c0 << (2 * j)) | (c1 << (2 * j + 1));
            }
            cb[t2][rh] = c;
            uint w0 = 0, w1 = 0;
            #pragma unroll
            for (int j = 0; j < 4; j++) {
                w0 |= ((c >> (2 * j)) & 1u)     << (j * 8 + 2 * q);
                w0 |= ((c >> (2 * j + 1)) & 1u) << (j * 8 + 2 * q + 1);
                w1 |= ((c >> (2 * j + 8)) & 1u) << (j * 8 + 2 * q);
                w1 |= ((c >> (2 * j + 9)) & 1u) << (j * 8 + 2 * q + 1);
            }
            w0 |= __shfl_xor_sync(0xffffffffu, w0, 1);
            w0 |= __shfl_xor_sync(0xffffffffu, w0, 2);
            w1 |= __shfl_xor_sync(0xffffffffu, w1, 1);
            w1 |= __shfl_xor_sync(0xffffffffu, w1, 2);
            if (q == 0) {
                int gn = n0 + rl;
                g_adjT[((size_t)b * 128 + (m0 >> 5) + wm * 2)     * NNODE + gn] = w0;
                g_adjT[((size_t)b * 128 + (m0 >> 5) + wm * 2 + 1) * NNODE + gn] = w1;
            }
        }
    }
    if (bi != bj) {
        #pragma unroll
        for (int idx = 0; idx < 16; idx++) {
            uint v = ((cb[0][0] >> idx) & 1u) << gid
                   | ((cb[0][1] >> idx) & 1u) << (gid + 8)
                   | ((cb[1][0] >> idx) & 1u) << (gid + 16)
                   | ((cb[1][1] >> idx) & 1u) << (gid + 24);
            v |= __shfl_xor_sync(0xffffffffu, v, 4);
            v |= __shfl_xor_sync(0xffffffffu, v, 8);
            v |= __shfl_xor_sync(0xffffffffu, v, 16);
            if (gid == 0) {
                int mg = m0 + wm * 64 + (idx >> 1) * 8 + 2 * lane + (idx & 1);
                g_adjT[((size_t)b * 128 + (n0 >> 5) + wn) * NNODE + mg] = v;
            }
        }
    }
}

// ---------------- fused degree + dinv + layer0 split ----------------
__global__ void __launch_bounds__(128) k_degsplit() {
    __shared__ int sc[4][32];
    __shared__ float sdv[32];

    int i0 = blockIdx.x * 32;
    int t = threadIdx.x, q = t >> 5, lane = t & 31;
    int gi = i0 + lane;
    int b = gi >> 12, nl = gi & 4095;
    const unsigned* base = g_adjT + (size_t)b * 128 * NNODE + nl;
    int c = 0;
    #pragma unroll 8
    for (int j = 0; j < 32; j++)
        c += __popc(base[(size_t)(q * 32 + j) * NNODE]);
    sc[q][lane] = c;
    __syncthreads();
    if (t < 32) {
        int tot = sc[0][t] + sc[1][t] + sc[2][t] + sc[3][t];
        float d = 1.0f / sqrtf((float)tot);
        g_dinv[i0 + t] = d;
        sdv[t] = d;
    }
    __syncthreads();

    int node = i0 + (t >> 2);
    float d = sdv[t >> 2];
    const float4* src = (const float4*)(g_xt + (size_t)node * 64 + (t & 3) * 16);
    unsigned short* o = g_xs + (size_t)node * 128 + (t & 3) * 16;
    #pragma unroll
    for (int j = 0; j < 4; j++) {
        float4 v = src[j];
        v.x *= d; v.y *= d; v.z *= d; v.w *= d;
        __nv_bfloat16 h0 = __float2bfloat16_rn(v.x);
        __nv_bfloat16 h1 = __float2bfloat16_rn(v.y);
        __nv_bfloat16 h2 = __float2bfloat16_rn(v.z);
        __nv_bfloat16 h3 = __float2bfloat16_rn(v.w);
        __nv_bfloat16 l0 = __float2bfloat16_rn(v.x - __bfloat162float(h0));
        __nv_bfloat16 l1 = __float2bfloat16_rn(v.y - __bfloat162float(h1));
        __nv_bfloat16 l2 = __float2bfloat16_rn(v.z - __bfloat162float(h2));
        __nv_bfloat16 l3 = __float2bfloat16_rn(v.w - __bfloat162float(h3));
        ushort4 hh, ll;
        hh.x = *(unsigned short*)&h0; hh.y = *(unsigned short*)&h1;
        hh.z = *(unsigned short*)&h2; hh.w = *(unsigned short*)&h3;
        ll.x = *(unsigned short*)&l0; ll.y = *(unsigned short*)&l1;
        ll.z = *(unsigned short*)&l2; ll.w = *(unsigned short*)&l3;
        *(ushort4*)(o + j * 4)      = hh;
        *(ushort4*)(o + 64 + j * 4) = ll;
    }
}

// ---------------- fused diffusion mma + FC + instance-norm + relu ----------------
// R14 structure; redundant end-of-loop barrier removed (top wait+sync orders
// compute(c-1) before stage(c+1) into the shared buffer).
__global__ void __launch_bounds__(128) k_mm(int layer, float* __restrict__ out_final,
                                            const float* __restrict__ W) {
    __shared__ union {
        unsigned short bs[2][64][SP];
        struct { float lxs[64][68]; float ws[64][64]; } e;
    } SM;

    int b = blockIdx.y, n0 = blockIdx.x * 64;
    int t = threadIdx.x, wr = t >> 5, lane = t & 31;
    int g = lane >> 2, tq = lane & 3;
    int rl8 = (lane & 7) + ((lane >> 3) & 1) * 8;
    int fg = (lane >> 4) * 8;

    const unsigned short* xsrc = (layer == 0) ? g_xs : g_xs2;
    const unsigned short* xsb = xsrc + (size_t)b * NNODE * 128;
    const unsigned* pa = g_adjT + (size_t)b * 128 * NNODE + (n0 + wr * 16 + g);
    const unsigned* pa8 = pa + 8;

    float cc[16][4];
    #pragma unroll
    for (int j = 0; j < 16; j++)
        #pragma unroll
        for (int q = 0; q < 4; q++) cc[j][q] = 0.f;

    int srow = t >> 4, schk = t & 15;
    uint sb0 = (uint)__cvta_generic_to_shared(&SM.bs[0][0][0]);
    uint sb1 = (uint)__cvta_generic_to_shared(&SM.bs[1][0][0]);

    #define MM_STAGE(cc_, bufaddr) do { \
        const unsigned short* src_ = xsb + (size_t)(cc_) * 64 * 128; \
        _Pragma("unroll") \
        for (int ps = 0; ps < 8; ps++) { \
            asm volatile("cp.async.ca.shared.global [%0], [%1], 16;" \
                :: "r"((bufaddr) + (uint)((srow + ps * 8) * SP + schk * 8) * 2), \
                   "l"(src_ + (size_t)(srow + ps * 8) * 128 + schk * 8)); \
        } \
        asm volatile("cp.async.commit_group;"); \
    } while (0)

    MM_STAGE(0, sb0);
    unsigned w0a = pa[0], w1a = pa[(size_t)4096];
    unsigned w0b = pa8[0], w1b = pa8[(size_t)4096];

    for (int c = 0; c < 64; c++) {
        asm volatile("cp.async.wait_group 0;" ::: "memory");
        __syncthreads();
        if (c + 1 < 64) MM_STAGE(c + 1, (c & 1) ? sb0 : sb1);
        unsigned nw0a = 0, nw1a = 0, nw0b = 0, nw1b = 0;
        if (c + 1 < 64) {
            nw0a = pa[(size_t)(2 * c + 2) * 4096];
            nw1a = pa[(size_t)(2 * c + 3) * 4096];
            nw0b = pa8[(size_t)(2 * c + 2) * 4096];
            nw1b = pa8[(size_t)(2 * c + 3) * 4096];
        }
        uint bb = (c & 1) ? sb1 : sb0;
        #pragma unroll
        for (int q = 0; q < 4; q++) {
            unsigned wA = (q < 2) ? w0a : w1a;
            unsigned wB = (q < 2) ? w0b : w1b;
            int s = ((q & 1) << 4) + 2 * tq;
            uint a0 = bfpair((wA >> s) & 3u);
            uint a2 = bfpair((wA >> (s + 8)) & 3u);
            uint a1 = bfpair((wB >> s) & 3u);
            uint a3 = bfpair((wB >> (s + 8)) & 3u);
            uint baddr = bb + (uint)(((q * 16 + rl8) * SP + fg) * 2);
            #pragma unroll
            for (int p = 0; p < 8; p++) {
                uint r0, r1, r2, r3;
                asm volatile(
                    "ldmatrix.sync.aligned.m8n8.x4.trans.shared.b16 {%0,%1,%2,%3}, [%4];"
                    : "=r"(r0), "=r"(r1), "=r"(r2), "=r"(r3)
                    : "r"(baddr + (uint)(p * 32)));
                MMA_BF16(cc[2 * p],     a0, a1, a2, a3, r0, r1);
                MMA_BF16(cc[2 * p + 1], a0, a1, a2, a3, r2, r3);
            }
        }
        w0a = nw0a; w1a = nw1a; w0b = nw0b; w1b = nw1b;
    }
    __syncthreads();

    {
        int lr0 = wr * 16 + g;
        float dn0 = g_dinv[b * NNODE + n0 + lr0];
        float dn1 = g_dinv[b * NNODE + n0 + lr0 + 8];
        #pragma unroll
        for (int j = 0; j < 8; j++) {
            int col = j * 8 + 2 * tq;
            float2 u0 = make_float2((cc[j][0] + cc[j + 8][0]) * dn0,
                                    (cc[j][1] + cc[j + 8][1]) * dn0);
            float2 u1 = make_float2((cc[j][2] + cc[j + 8][2]) * dn1,
                                    (cc[j][3] + cc[j + 8][3]) * dn1);
            *(float2*)&SM.e.lxs[lr0][col]     = u0;
            *(float2*)&SM.e.lxs[lr0 + 8][col] = u1;
        }
    }
    {
        int c2 = t >> 1, fh = (t & 1) * 32;
        #pragma unroll
        for (int j = 0; j < 8; j++)
            *(float4*)&SM.e.ws[c2][fh + j * 4] = *(const float4*)(W + c2 * 64 + fh + j * 4);
    }
    __syncthreads();

    int row = t >> 1, fh = (t & 1) * 32;
    ull h[16];
    #pragma unroll
    for (int j = 0; j < 16; j++) h[j] = 0ULL;
    #pragma unroll 8
    for (int c = 0; c < 64; c++) {
        ull a2 = pack2(SM.e.lxs[row][c]);
        const ulonglong2* w2 = (const ulonglong2*)&SM.e.ws[c][fh];
        #pragma unroll
        for (int j = 0; j < 4; j++) {
            ulonglong2 u0 = w2[2 * j];
            ulonglong2 u1 = w2[2 * j + 1];
            fma2(h[4 * j],     a2, u0.x);
            fma2(h[4 * j + 1], a2, u0.y);
            fma2(h[4 * j + 2], a2, u1.x);
            fma2(h[4 * j + 3], a2, u1.y);
        }
    }
    float hv[32];
    #pragma unroll
    for (int j = 0; j < 16; j++) { F2U u; u.u = h[j]; hv[2 * j] = u.f.x; hv[2 * j + 1] = u.f.y; }

    float sum = 0.f;
    #pragma unroll
    for (int j = 0; j < 32; j++) sum += hv[j];
    sum += __shfl_xor_sync(0xffffffffu, sum, 1);
    float mean = sum * (1.f / 64.f);
    float vq = 0.f;
    #pragma unroll
    for (int j = 0; j < 32; j++) { float d = hv[j] - mean; vq += d * d; }
    vq += __shfl_xor_sync(0xffffffffu, vq, 1);
    float inv = 1.0f / sqrtf(vq * (1.f / 64.f) + EPSI);

    int gnode = b * NNODE + n0 + row;
    if (layer == 0) {
        float d = g_dinv[gnode];
        unsigned short* o = g_xs2 + (size_t)gnode * 128 + fh;
        #pragma unroll
        for (int f4 = 0; f4 < 8; f4++) {
            ushort4 hh, ll;
            unsigned short* hp = &hh.x;
            unsigned short* lp = &ll.x;
            #pragma unroll
            for (int q = 0; q < 4; q++) {
                float y = fmaxf((hv[f4 * 4 + q] - mean) * inv, 0.f) * d;
                __nv_bfloat16 hb = __float2bfloat16_rn(y);
                __nv_bfloat16 lb = __float2bfloat16_rn(y - __bfloat162float(hb));
                hp[q] = *(unsigned short*)&hb;
                lp[q] = *(unsigned short*)&lb;
            }
            *(ushort4*)(o + f4 * 4)      = hh;
            *(ushort4*)(o + 64 + f4 * 4) = ll;
        }
    } else {
        float* op = out_final + (size_t)gnode * 64 + fh;
        #pragma unroll
        for (int f4 = 0; f4 < 8; f4++) {
            float4 ov;
            ov.x = fmaxf((hv[f4 * 4 + 0] - mean) * inv, 0.f);
            ov.y = fmaxf((hv[f4 * 4 + 1] - mean) * inv, 0.f);
            ov.z = fmaxf((hv[f4 * 4 + 2] - mean) * inv, 0.f);
            ov.w = fmaxf((hv[f4 * 4 + 3] - mean) * inv, 0.f);
            *(float4*)(op + f4 * 4) = ov;
        }
    }
}

// ---------------- launch ----------------
extern "C" void kernel_launch(void* const* d_in, const int* in_sizes, int n_in,
                              void* d_out, int out_size) {
    const float* x  = (const float*)d_in[0];
    const float* W0 = (const float*)d_in[1];
    const float* W1 = (const float*)d_in[2];
    float* out = (float*)d_out;

    k_prep<<<dim3(64, 4), 256>>>(x);
    k_gram<<<dim3(528, 4), 256>>>();
    k_degsplit<<<512, 128>>>();
    k_mm<<<dim3(64, 4), 128>>>(0, nullptr, W0);
    k_mm<<<dim3(64, 4), 128>>>(1, out, W1);
}